// round 15
// baseline (speedup 1.0000x reference)
#include <cuda_runtime.h>
#include <cuda_bf16.h>
#include <math.h>
#include <stdint.h>

#define D_MODEL 1024
#define SEQ     2048
#define BSZ     4
#define M_TOTAL (BSZ*SEQ)   /* 8192 */
#define NHEAD   16
#define DHEAD   64
#define LN_EPS  1e-5f
#define LOG2E   1.4426950408889634f

__device__ __forceinline__ uint32_t smem_to_u32(const void* p) {
    uint32_t a;
    asm("{ .reg .u64 t; cvta.to.shared.u64 t, %1; cvt.u32.u64 %0, t; }"
        : "=r"(a) : "l"(p));
    return a;
}

#define LDMX4(r, addr) \
    asm volatile("ldmatrix.sync.aligned.m8n8.x4.shared.b16 {%0,%1,%2,%3}, [%4];" \
        : "=r"((r)[0]), "=r"((r)[1]), "=r"((r)[2]), "=r"((r)[3]) : "r"(addr))

#define LDMX4T(r, addr) \
    asm volatile("ldmatrix.sync.aligned.m8n8.x4.trans.shared.b16 {%0,%1,%2,%3}, [%4];" \
        : "=r"((r)[0]), "=r"((r)[1]), "=r"((r)[2]), "=r"((r)[3]) : "r"(addr))

#define MMA_BF16(d, a, b) \
    asm volatile("mma.sync.aligned.m16n8k16.row.col.f32.bf16.bf16.f32 " \
        "{%0,%1,%2,%3}, {%4,%5,%6,%7}, {%8,%9}, {%0,%1,%2,%3};" \
        : "+f"((d)[0]), "+f"((d)[1]), "+f"((d)[2]), "+f"((d)[3]) \
        : "r"((a)[0]), "r"((a)[1]), "r"((a)[2]), "r"((a)[3]), \
          "r"((b)[0]), "r"((b)[1]))

#define CP_ASYNC16(saddr, gptr) \
    asm volatile("cp.async.cg.shared.global [%0], [%1], 16;" \
                 :: "r"((uint32_t)(saddr)), "l"(gptr))
#define CP_COMMIT() asm volatile("cp.async.commit_group;" ::: "memory")
#define CP_WAIT1()  asm volatile("cp.async.wait_group 1;" ::: "memory")
#define CP_WAIT0()  asm volatile("cp.async.wait_group 0;" ::: "memory")

#define EX2(d, x) asm("ex2.approx.ftz.f32 %0, %1;" : "=f"(d) : "f"(x))
#define PACKBF2(r, x0, x1) \
    asm("cvt.rn.bf16x2.f32 %0, %1, %2;" : "=r"(r) : "f"(x1), "f"(x0))

/* ---- scratch (no allocations; __device__ globals) ---- */
__device__ __align__(16) float g_pre[M_TOTAL*D_MODEL];

__device__ __align__(16) __nv_bfloat16 bq_h [M_TOTAL*D_MODEL];
__device__ __align__(16) __nv_bfloat16 bk_h [M_TOTAL*D_MODEL];
__device__ __align__(16) __nv_bfloat16 bv_h [M_TOTAL*D_MODEL];
__device__ __align__(16) __nv_bfloat16 bwq_h[D_MODEL*D_MODEL];
__device__ __align__(16) __nv_bfloat16 bwk_h[D_MODEL*D_MODEL];
__device__ __align__(16) __nv_bfloat16 bwv_h[D_MODEL*D_MODEL];
__device__ __align__(16) __nv_bfloat16 bwo_h[D_MODEL*D_MODEL];
__device__ __align__(16) __nv_bfloat16 oq_h [M_TOTAL*D_MODEL];
__device__ __align__(16) __nv_bfloat16 ok_h [M_TOTAL*D_MODEL];
__device__ __align__(16) __nv_bfloat16 ov_h [M_TOTAL*D_MODEL];
__device__ __align__(16) __nv_bfloat16 bctx_h[M_TOTAL*D_MODEL];

/* ============================================================
 * fp32 -> bf16 conversions
 * ============================================================ */
__device__ __forceinline__ void conv4(const float* __restrict__ src,
                                      __nv_bfloat16* __restrict__ hi, int i)
{
    float4 v = ((const float4*)src)[i];
    uint32_t p0, p1;
    PACKBF2(p0, v.x, v.y);
    PACKBF2(p1, v.z, v.w);
    uint32_t* H = (uint32_t*)hi;
    H[2*i]   = p0;
    H[2*i+1] = p1;
}

__global__ __launch_bounds__(256)
void act_conv(const float* __restrict__ q, const float* __restrict__ k,
              const float* __restrict__ v)
{
    int i = blockIdx.x * 256 + threadIdx.x;
    int z = blockIdx.y;
    const float* src = (z == 0) ? q : ((z == 1) ? k : v);
    __nv_bfloat16* hi = (z == 0) ? bq_h : ((z == 1) ? bk_h : bv_h);
    conv4(src, hi, i);
}

__global__ __launch_bounds__(256)
void w_conv(const float* __restrict__ wq, const float* __restrict__ wk,
            const float* __restrict__ wv, const float* __restrict__ wo)
{
    int i = blockIdx.x * 256 + threadIdx.x;
    int z = blockIdx.y;
    const float* src = (z == 0) ? wq : ((z == 1) ? wk : ((z == 2) ? wv : wo));
    __nv_bfloat16* hi = (z == 0) ? bwq_h : ((z == 1) ? bwk_h : ((z == 2) ? bwv_h : bwo_h));
    conv4(src, hi, i);
}

/* ============================================================
 * Single-bf16 GEMM: CTA 256x128, kblock 64, 2-stage cp.async
 * ============================================================ */
#define GSTAGE1 49152
#define GEMM1_SMEM (2*GSTAGE1)   /* 98304 */

__device__ __forceinline__ void gemm1_load(
    uint32_t sb, int st, int kb, int tid, int m0, int n0,
    const __nv_bfloat16* Ah, const __nv_bfloat16* Bh)
{
    const uint32_t stb = sb + st * GSTAGE1;
    const int r0 = tid >> 3, c = tid & 7;
    {
        const __nv_bfloat16* S = Ah + (size_t)m0 * D_MODEL + kb * 64;
#pragma unroll
        for (int p = 0; p < 8; p++) {
            int r = p * 32 + r0;
            const char* g = (const char*)(S + (size_t)r * D_MODEL) + c * 16;
            CP_ASYNC16(stb + r * 128 + ((c ^ (r & 7)) * 16), g);
        }
    }
    {
        const __nv_bfloat16* S = Bh + (size_t)n0 * D_MODEL + kb * 64;
#pragma unroll
        for (int p = 0; p < 4; p++) {
            int r = p * 32 + r0;
            const char* g = (const char*)(S + (size_t)r * D_MODEL) + c * 16;
            CP_ASYNC16(stb + 32768 + r * 128 + ((c ^ (r & 7)) * 16), g);
        }
    }
}

__device__ __forceinline__ void gemm1_compute(
    uint32_t sb, int st, int lane, int wm, int wn, float acc[4][8][4])
{
    const uint32_t stb = sb + st * GSTAGE1;
#pragma unroll
    for (int ks = 0; ks < 4; ks++) {
        uint32_t ahf[4][4];
        const int arow = wm + (lane & 15);
        const int ac = ks * 2 + (lane >> 4);
#pragma unroll
        for (int mt = 0; mt < 4; mt++) {
            int r = arow + mt * 16;
            LDMX4(ahf[mt], stb + r * 128 + ((ac ^ (r & 7)) * 16));
        }
        const int brow0 = wn + ((lane >> 4) << 3) + (lane & 7);
        const int bc = ks * 2 + ((lane >> 3) & 1);
#pragma unroll
        for (int ntp = 0; ntp < 4; ntp++) {
            int r = brow0 + ntp * 16;
            uint32_t bhf[4];
            LDMX4(bhf, stb + 32768 + r * 128 + ((bc ^ (r & 7)) * 16));
#pragma unroll
            for (int hf = 0; hf < 2; hf++) {
                const int nt = ntp * 2 + hf;
#pragma unroll
                for (int mt = 0; mt < 4; mt++) MMA_BF16(acc[mt][nt], ahf[mt], &bhf[hf*2]);
            }
        }
    }
}

__global__ __launch_bounds__(256, 1)
void qkv_gemm()
{
    extern __shared__ __align__(128) char smem[];
    const uint32_t sb = smem_to_u32(smem);
    const int tid = threadIdx.x;
    const int lane = tid & 31, wid = tid >> 5;
    const int wm = (wid >> 1) * 64, wn = (wid & 1) * 64;
    const int n0 = blockIdx.x * 128, m0 = blockIdx.y * 256;
    const int z = blockIdx.z;

    const __nv_bfloat16* Ah = (z == 0) ? bq_h : ((z == 1) ? bk_h : bv_h);
    const __nv_bfloat16* Bh = (z == 0) ? bwq_h : ((z == 1) ? bwk_h : bwv_h);
    __nv_bfloat16* Oh = (z == 0) ? oq_h : ((z == 1) ? ok_h : ov_h);

    float acc[4][8][4];
#pragma unroll
    for (int mt = 0; mt < 4; mt++)
#pragma unroll
        for (int nt = 0; nt < 8; nt++)
#pragma unroll
            for (int e = 0; e < 4; e++) acc[mt][nt][e] = 0.f;

    gemm1_load(sb, 0, 0, tid, m0, n0, Ah, Bh);
    CP_COMMIT();

    for (int kb = 0; kb < 16; kb++) {
        if (kb < 15) {
            gemm1_load(sb, (kb + 1) & 1, kb + 1, tid, m0, n0, Ah, Bh);
            CP_COMMIT();
            CP_WAIT1();
        } else {
            CP_WAIT0();
        }
        __syncthreads();
        gemm1_compute(sb, kb & 1, lane, wm, wn, acc);
        __syncthreads();
    }

    const int cr = lane >> 2, cc = (lane & 3) * 2;
    const int h = (n0 + wn) >> 6;
#pragma unroll
    for (int mt = 0; mt < 4; mt++) {
#pragma unroll
        for (int rr = 0; rr < 2; rr++) {
            const int m = m0 + wm + mt * 16 + cr + rr * 8;
            const int bb = m >> 11, s = m & 2047;
            size_t rowoff = (((size_t)bb * NHEAD + h) * SEQ + s) * DHEAD;
#pragma unroll
            for (int nt = 0; nt < 8; nt++) {
                int d = nt * 8 + cc;
                uint32_t pk;
                PACKBF2(pk, acc[mt][nt][rr*2], acc[mt][nt][rr*2+1]);
                *(uint32_t*)(Oh + rowoff + d) = pk;
            }
        }
    }
}

__global__ __launch_bounds__(256, 1)
void out_gemm(const float* __restrict__ Res)
{
    extern __shared__ __align__(128) char smem[];
    const uint32_t sb = smem_to_u32(smem);
    const int tid = threadIdx.x;
    const int lane = tid & 31, wid = tid >> 5;
    const int wm = (wid >> 1) * 64, wn = (wid & 1) * 64;
    const int n0 = blockIdx.x * 128, m0 = blockIdx.y * 256;

    float acc[4][8][4];
#pragma unroll
    for (int mt = 0; mt < 4; mt++)
#pragma unroll
        for (int nt = 0; nt < 8; nt++)
#pragma unroll
            for (int e = 0; e < 4; e++) acc[mt][nt][e] = 0.f;

    gemm1_load(sb, 0, 0, tid, m0, n0, bctx_h, bwo_h);
    CP_COMMIT();

    for (int kb = 0; kb < 16; kb++) {
        if (kb < 15) {
            gemm1_load(sb, (kb + 1) & 1, kb + 1, tid, m0, n0, bctx_h, bwo_h);
            CP_COMMIT();
            CP_WAIT1();
        } else {
            CP_WAIT0();
        }
        __syncthreads();
        gemm1_compute(sb, kb & 1, lane, wm, wn, acc);
        __syncthreads();
    }

    const int cr = lane >> 2, cc = (lane & 3) * 2;
#pragma unroll
    for (int mt = 0; mt < 4; mt++) {
#pragma unroll
        for (int rr = 0; rr < 2; rr++) {
            const int m = m0 + wm + mt * 16 + cr + rr * 8;
            const float* rp = Res + (size_t)m * D_MODEL + n0 + wn;
            float* dst = g_pre + (size_t)m * D_MODEL + n0 + wn;
#pragma unroll
            for (int nt = 0; nt < 8; nt++) {
                int d = nt * 8 + cc;
                float2 rv = *(const float2*)(rp + d);
                *(float2*)(dst + d) = make_float2(acc[mt][nt][rr*2] + rv.x,
                                                  acc[mt][nt][rr*2+1] + rv.y);
            }
        }
    }
}

/* ============================================================
 * flash_mma: single-bf16, 128 Q rows/block, 4 warps x 32 rows,
 * K/V tile 64, 2-stage cp.async, static-offset softmax,
 * A-fragment reuse (each B ldmatrix feeds 4 MMAs).
 * smem: Q(16K) | st0 KV(16K) | st1 KV(16K) | msk 2x256B
 * ============================================================ */
#define FTHREADS   128
#define FSH_KV     16384
#define FKV_STAGE  16384
#define FSH_MSK    (16384 + 2*16384)   /* 49152 */
#define FLASH_SMEM (49152 + 512)

__device__ __forceinline__ void flash_load_kv(
    uint32_t sb, int st, int kt, int tid, size_t bh_base, const float* maskb)
{
    const int sk0 = kt * 64;
    const uint32_t stb = sb + FSH_KV + st * FKV_STAGE;
#pragma unroll
    for (int t = 0; t < 2; t++) {
        const __nv_bfloat16* S = (t ? ov_h : ok_h) + bh_base + (size_t)sk0 * DHEAD;
        const uint32_t dstb = stb + t * 8192;
#pragma unroll
        for (int it = 0; it < 4; it++) {
            int flat = tid + it * FTHREADS;
            int r = flat >> 3, c = flat & 7;
            const char* g = (const char*)(S + (size_t)r * DHEAD) + c * 16;
            CP_ASYNC16(dstb + r * 128 + ((c ^ (r & 7)) * 16), g);
        }
    }
    if (tid < 16)
        CP_ASYNC16(sb + FSH_MSK + st * 256 + tid * 16, maskb + sk0 + tid * 4);
}

__global__ __launch_bounds__(FTHREADS)
void flash_mma(const float* __restrict__ mask)
{
    extern __shared__ __align__(128) char fsm[];
    const uint32_t sb = smem_to_u32(fsm);

    const int tid = threadIdx.x;
    const int lane = tid & 31, wid = tid >> 5;
    const int wq = wid * 32;                 /* 4 warps x 32 rows = 128 */
    const int bh = blockIdx.y;
    const int b  = bh >> 4;
    const int h  = bh & 15;
    const int q0 = blockIdx.x * 128;
    const size_t bh_base = (size_t)bh * SEQ * DHEAD;
    const float* maskb = mask + b * SEQ;

    /* Q tile (128 rows) into swizzled smem */
    {
        const __nv_bfloat16* S = oq_h + bh_base + (size_t)q0 * DHEAD;
#pragma unroll
        for (int it = 0; it < 8; it++) {
            int flat = tid + it * FTHREADS;
            int r = flat >> 3, c = flat & 7;
            uint4 val = *(const uint4*)((const char*)(S + (size_t)r * DHEAD) + c * 16);
            uint32_t sw = sb + r * 128 + ((c ^ (r & 7)) * 16);
            asm volatile("st.shared.v4.b32 [%0], {%1,%2,%3,%4};"
                         :: "r"(sw), "r"(val.x), "r"(val.y), "r"(val.z), "r"(val.w));
        }
    }

    flash_load_kv(sb, 0, 0, tid, bh_base, maskb);
    CP_COMMIT();

    /* hoist Q fragments (2 m-subtiles) into registers */
    __syncthreads();
    uint32_t qfh[2][4][4];
#pragma unroll
    for (int ms = 0; ms < 2; ms++)
#pragma unroll
        for (int ks = 0; ks < 4; ks++) {
            const int ar = wq + ms * 16 + (lane & 15);
            const int ac = ks * 2 + (lane >> 4);
            LDMX4(qfh[ms][ks], sb + ar * 128 + ((ac ^ (ar & 7)) * 16));
        }

    float l[2][2] = {{0.f, 0.f}, {0.f, 0.f}};
    float o[2][8][4];
#pragma unroll
    for (int ms = 0; ms < 2; ms++)
#pragma unroll
        for (int nt = 0; nt < 8; nt++)
#pragma unroll
            for (int e = 0; e < 4; e++) o[ms][nt][e] = 0.f;

    const int c0 = (lane & 3) * 2;
    const float SCALE = 0.125f * LOG2E;
    const float MSCALE = -1e9f * LOG2E;
    const float FMAX_OFF = 16.0f;

    for (int kt = 0; kt < SEQ / 64; kt++) {
        const int st = kt & 1;
        if (kt < SEQ/64 - 1) {
            flash_load_kv(sb, st ^ 1, kt + 1, tid, bh_base, maskb);
            CP_COMMIT();
            CP_WAIT1();
        } else {
            CP_WAIT0();
        }
        __syncthreads();

        const uint32_t kvb = sb + FSH_KV + st * FKV_STAGE;
        const float* msk_s = (const float*)(fsm + FSH_MSK + st * 256);

        /* S = Q K^T : each B ldmatrix feeds both m-subtiles */
        float s[2][8][4];
#pragma unroll
        for (int ms = 0; ms < 2; ms++)
#pragma unroll
            for (int nt = 0; nt < 8; nt++)
#pragma unroll
                for (int e = 0; e < 4; e++) s[ms][nt][e] = 0.f;
#pragma unroll
        for (int ks = 0; ks < 4; ks++) {
            const int brow0 = ((lane >> 4) << 3) + (lane & 7);
            const int bc = ks * 2 + ((lane >> 3) & 1);
#pragma unroll
            for (int ntp = 0; ntp < 4; ntp++) {
                int r = brow0 + ntp * 16;
                uint32_t bhf[4];
                LDMX4(bhf, kvb + r * 128 + ((bc ^ (r & 7)) * 16));
#pragma unroll
                for (int hf = 0; hf < 2; hf++)
#pragma unroll
                    for (int ms = 0; ms < 2; ms++)
                        MMA_BF16(s[ms][ntp*2 + hf], qfh[ms][ks], &bhf[hf*2]);
            }
        }

        /* static-offset softmax + immediate pack (frees s) */
        uint32_t ah[2][4][4];
#pragma unroll
        for (int nt = 0; nt < 8; nt++) {
            float mv0 = fmaf(msk_s[nt*8 + c0],     MSCALE, -FMAX_OFF);
            float mv1 = fmaf(msk_s[nt*8 + c0 + 1], MSCALE, -FMAX_OFF);
#pragma unroll
            for (int ms = 0; ms < 2; ms++) {
                EX2(s[ms][nt][0], fmaf(s[ms][nt][0], SCALE, mv0));
                EX2(s[ms][nt][1], fmaf(s[ms][nt][1], SCALE, mv1));
                EX2(s[ms][nt][2], fmaf(s[ms][nt][2], SCALE, mv0));
                EX2(s[ms][nt][3], fmaf(s[ms][nt][3], SCALE, mv1));
                l[ms][0] += s[ms][nt][0] + s[ms][nt][1];
                l[ms][1] += s[ms][nt][2] + s[ms][nt][3];
                const int ks = nt >> 1, half = nt & 1;
                PACKBF2(ah[ms][ks][half*2 + 0], s[ms][nt][0], s[ms][nt][1]);
                PACKBF2(ah[ms][ks][half*2 + 1], s[ms][nt][2], s[ms][nt][3]);
            }
        }

        /* PV : each V ldmatrix feeds both m-subtiles */
#pragma unroll
        for (int ks = 0; ks < 4; ks++) {
            const int vr = ks*16 + (lane & 15);
            const int vc = (lane >> 4);
#pragma unroll
            for (int ntp = 0; ntp < 4; ntp++) {
                int c = ntp*2 + vc;
                uint32_t vh[4];
                LDMX4T(vh, kvb + 8192 + vr * 128 + ((c ^ (vr & 7)) * 16));
#pragma unroll
                for (int hf = 0; hf < 2; hf++)
#pragma unroll
                    for (int ms = 0; ms < 2; ms++)
                        MMA_BF16(o[ms][ntp*2 + hf], ah[ms][ks], &vh[hf*2]);
            }
        }
        __syncthreads();
    }

    /* deferred l reduction across the quad */
#pragma unroll
    for (int ms = 0; ms < 2; ms++) {
        l[ms][0] += __shfl_xor_sync(0xffffffffu, l[ms][0], 1);
        l[ms][0] += __shfl_xor_sync(0xffffffffu, l[ms][0], 2);
        l[ms][1] += __shfl_xor_sync(0xffffffffu, l[ms][1], 1);
        l[ms][1] += __shfl_xor_sync(0xffffffffu, l[ms][1], 2);
    }

    /* epilogue: ctx single bf16, packed cvt */
#pragma unroll
    for (int ms = 0; ms < 2; ms++) {
        const float inv0 = 1.f / l[ms][0], inv1 = 1.f / l[ms][1];
        const int r0 = q0 + wq + ms * 16 + (lane >> 2);
        const size_t ro0 = ((size_t)b * SEQ + r0) * D_MODEL + h * DHEAD;
        const size_t ro1 = ((size_t)b * SEQ + r0 + 8) * D_MODEL + h * DHEAD;
#pragma unroll
        for (int nt = 0; nt < 8; nt++) {
            int d = nt * 8 + c0;
            uint32_t p0, p1;
            PACKBF2(p0, o[ms][nt][0] * inv0, o[ms][nt][1] * inv0);
            PACKBF2(p1, o[ms][nt][2] * inv1, o[ms][nt][3] * inv1);
            *(uint32_t*)(bctx_h + ro0 + d) = p0;
            *(uint32_t*)(bctx_h + ro1 + d) = p1;
        }
    }
}

/* ============================================================
 * LayerNorm
 * ============================================================ */
__global__ __launch_bounds__(256)
void ln_kernel(const float* __restrict__ gamma, const float* __restrict__ beta,
               float* __restrict__ out)
{
    const int row = blockIdx.x;
    const int tid = threadIdx.x;
    const float* x = &g_pre[(size_t)row * D_MODEL];

    float4 v = *(const float4*)&x[tid * 4];
    float s  = v.x + v.y + v.z + v.w;
    float ss = v.x*v.x + v.y*v.y + v.z*v.z + v.w*v.w;
#pragma unroll
    for (int off = 16; off >= 1; off >>= 1) {
        s  += __shfl_xor_sync(0xffffffffu, s, off);
        ss += __shfl_xor_sync(0xffffffffu, ss, off);
    }
    __shared__ float rs[8], rss[8];
    __shared__ float mu_s, inv_s;
    if ((tid & 31) == 0) { rs[tid >> 5] = s; rss[tid >> 5] = ss; }
    __syncthreads();
    if (tid == 0) {
        float S = 0.f, SS = 0.f;
#pragma unroll
        for (int i = 0; i < 8; i++) { S += rs[i]; SS += rss[i]; }
        float mu  = S * (1.f / D_MODEL);
        float var = SS * (1.f / D_MODEL) - mu * mu;
        mu_s = mu;
        inv_s = rsqrtf(var + LN_EPS);
    }
    __syncthreads();
    const float mu = mu_s, inv = inv_s;
    float4 g  = *(const float4*)&gamma[tid * 4];
    float4 be = *(const float4*)&beta[tid * 4];
    float4 r;
    r.x = (v.x - mu) * inv * g.x + be.x;
    r.y = (v.y - mu) * inv * g.y + be.y;
    r.z = (v.z - mu) * inv * g.z + be.z;
    r.w = (v.w - mu) * inv * g.w + be.w;
    *(float4*)&out[(size_t)row * D_MODEL + tid * 4] = r;
}

/* ============================================================ */
extern "C" void kernel_launch(void* const* d_in, const int* in_sizes, int n_in,
                              void* d_out, int out_size)
{
    const float* q     = (const float*)d_in[0];
    const float* k     = (const float*)d_in[1];
    const float* v     = (const float*)d_in[2];
    const float* mask  = (const float*)d_in[3];
    const float* Wq    = (const float*)d_in[4];
    const float* Wk    = (const float*)d_in[5];
    const float* Wv    = (const float*)d_in[6];
    const float* Wo    = (const float*)d_in[7];
    const float* gamma = (const float*)d_in[8];
    const float* beta  = (const float*)d_in[9];
    float* out = (float*)d_out;

    cudaFuncSetAttribute(qkv_gemm, cudaFuncAttributeMaxDynamicSharedMemorySize, GEMM1_SMEM);
    cudaFuncSetAttribute(out_gemm, cudaFuncAttributeMaxDynamicSharedMemorySize, GEMM1_SMEM);
    cudaFuncSetAttribute(flash_mma, cudaFuncAttributeMaxDynamicSharedMemorySize, FLASH_SMEM);

    const int NA4 = M_TOTAL*D_MODEL/4;
    const int NW4 = D_MODEL*D_MODEL/4;

    act_conv<<<dim3(NA4/256, 3), 256>>>(q, k, v);
    w_conv<<<dim3(NW4/256, 4), 256>>>(Wq, Wk, Wv, Wo);

    qkv_gemm<<<dim3(D_MODEL/128, M_TOTAL/256, 3), 256, GEMM1_SMEM>>>();

    flash_mma<<<dim3(SEQ/128, BSZ*NHEAD), FTHREADS, FLASH_SMEM>>>(mask);

    out_gemm<<<dim3(D_MODEL/128, M_TOTAL/256), 256, GEMM1_SMEM>>>(q);

    ln_kernel<<<M_TOTAL, 256>>>(gamma, beta, out);
}

// round 16
// speedup vs baseline: 1.0728x; 1.0728x over previous
#include <cuda_runtime.h>
#include <cuda_bf16.h>
#include <math.h>
#include <stdint.h>

#define D_MODEL 1024
#define SEQ     2048
#define BSZ     4
#define M_TOTAL (BSZ*SEQ)   /* 8192 */
#define NHEAD   16
#define DHEAD   64
#define LN_EPS  1e-5f
#define LOG2E   1.4426950408889634f

__device__ __forceinline__ uint32_t smem_to_u32(const void* p) {
    uint32_t a;
    asm("{ .reg .u64 t; cvta.to.shared.u64 t, %1; cvt.u32.u64 %0, t; }"
        : "=r"(a) : "l"(p));
    return a;
}

#define LDMX4(r, addr) \
    asm volatile("ldmatrix.sync.aligned.m8n8.x4.shared.b16 {%0,%1,%2,%3}, [%4];" \
        : "=r"((r)[0]), "=r"((r)[1]), "=r"((r)[2]), "=r"((r)[3]) : "r"(addr))

#define LDMX4T(r, addr) \
    asm volatile("ldmatrix.sync.aligned.m8n8.x4.trans.shared.b16 {%0,%1,%2,%3}, [%4];" \
        : "=r"((r)[0]), "=r"((r)[1]), "=r"((r)[2]), "=r"((r)[3]) : "r"(addr))

#define MMA_BF16(d, a, b) \
    asm volatile("mma.sync.aligned.m16n8k16.row.col.f32.bf16.bf16.f32 " \
        "{%0,%1,%2,%3}, {%4,%5,%6,%7}, {%8,%9}, {%0,%1,%2,%3};" \
        : "+f"((d)[0]), "+f"((d)[1]), "+f"((d)[2]), "+f"((d)[3]) \
        : "r"((a)[0]), "r"((a)[1]), "r"((a)[2]), "r"((a)[3]), \
          "r"((b)[0]), "r"((b)[1]))

#define CP_ASYNC16(saddr, gptr) \
    asm volatile("cp.async.cg.shared.global [%0], [%1], 16;" \
                 :: "r"((uint32_t)(saddr)), "l"(gptr))
#define CP_COMMIT() asm volatile("cp.async.commit_group;" ::: "memory")
#define CP_WAIT1()  asm volatile("cp.async.wait_group 1;" ::: "memory")
#define CP_WAIT0()  asm volatile("cp.async.wait_group 0;" ::: "memory")

#define EX2(d, x) asm("ex2.approx.ftz.f32 %0, %1;" : "=f"(d) : "f"(x))
#define PACKBF2(r, x0, x1) \
    asm("cvt.rn.bf16x2.f32 %0, %1, %2;" : "=r"(r) : "f"(x1), "f"(x0))

/* ---- scratch (no allocations; __device__ globals) ---- */
__device__ __align__(16) float g_pre[M_TOTAL*D_MODEL];

__device__ __align__(16) __nv_bfloat16 bq_h [M_TOTAL*D_MODEL];
__device__ __align__(16) __nv_bfloat16 bk_h [M_TOTAL*D_MODEL];
__device__ __align__(16) __nv_bfloat16 bv_h [M_TOTAL*D_MODEL];
__device__ __align__(16) __nv_bfloat16 bwq_h[D_MODEL*D_MODEL];
__device__ __align__(16) __nv_bfloat16 bwk_h[D_MODEL*D_MODEL];
__device__ __align__(16) __nv_bfloat16 bwv_h[D_MODEL*D_MODEL];
__device__ __align__(16) __nv_bfloat16 bwo_h[D_MODEL*D_MODEL];
__device__ __align__(16) __nv_bfloat16 oq_h [M_TOTAL*D_MODEL];
__device__ __align__(16) __nv_bfloat16 ok_h [M_TOTAL*D_MODEL];
__device__ __align__(16) __nv_bfloat16 ov_h [M_TOTAL*D_MODEL];
__device__ __align__(16) __nv_bfloat16 bctx_h[M_TOTAL*D_MODEL];

/* ============================================================
 * fp32 -> bf16 conversions
 * ============================================================ */
__device__ __forceinline__ void conv4(const float* __restrict__ src,
                                      __nv_bfloat16* __restrict__ hi, int i)
{
    float4 v = ((const float4*)src)[i];
    uint32_t p0, p1;
    PACKBF2(p0, v.x, v.y);
    PACKBF2(p1, v.z, v.w);
    uint32_t* H = (uint32_t*)hi;
    H[2*i]   = p0;
    H[2*i+1] = p1;
}

__global__ __launch_bounds__(256)
void act_conv(const float* __restrict__ q, const float* __restrict__ k,
              const float* __restrict__ v)
{
    int i = blockIdx.x * 256 + threadIdx.x;
    int z = blockIdx.y;
    const float* src = (z == 0) ? q : ((z == 1) ? k : v);
    __nv_bfloat16* hi = (z == 0) ? bq_h : ((z == 1) ? bk_h : bv_h);
    conv4(src, hi, i);
}

__global__ __launch_bounds__(256)
void w_conv(const float* __restrict__ wq, const float* __restrict__ wk,
            const float* __restrict__ wv, const float* __restrict__ wo)
{
    int i = blockIdx.x * 256 + threadIdx.x;
    int z = blockIdx.y;
    const float* src = (z == 0) ? wq : ((z == 1) ? wk : ((z == 2) ? wv : wo));
    __nv_bfloat16* hi = (z == 0) ? bwq_h : ((z == 1) ? bwk_h : ((z == 2) ? bwv_h : bwo_h));
    conv4(src, hi, i);
}

/* ============================================================
 * Single-bf16 GEMM: CTA 128x128, 8 warps (warp 64x32),
 * kblock 64, 2-stage cp.async. stage = A(16K) + B(16K) = 32K.
 * 2 CTAs/SM (16 warps).
 * ============================================================ */
#define GSTAGE1 32768
#define GEMM1_SMEM (2*GSTAGE1)   /* 65536 */

__device__ __forceinline__ void gemm1_load(
    uint32_t sb, int st, int kb, int tid, int m0, int n0,
    const __nv_bfloat16* Ah, const __nv_bfloat16* Bh)
{
    const uint32_t stb = sb + st * GSTAGE1;
    const int r0 = tid >> 3, c = tid & 7;
    {
        const __nv_bfloat16* S = Ah + (size_t)m0 * D_MODEL + kb * 64;
#pragma unroll
        for (int p = 0; p < 4; p++) {
            int r = p * 32 + r0;
            const char* g = (const char*)(S + (size_t)r * D_MODEL) + c * 16;
            CP_ASYNC16(stb + r * 128 + ((c ^ (r & 7)) * 16), g);
        }
    }
    {
        const __nv_bfloat16* S = Bh + (size_t)n0 * D_MODEL + kb * 64;
#pragma unroll
        for (int p = 0; p < 4; p++) {
            int r = p * 32 + r0;
            const char* g = (const char*)(S + (size_t)r * D_MODEL) + c * 16;
            CP_ASYNC16(stb + 16384 + r * 128 + ((c ^ (r & 7)) * 16), g);
        }
    }
}

/* warp tile 64x32: acc[4 mt][4 nt][4] */
__device__ __forceinline__ void gemm1_compute(
    uint32_t sb, int st, int lane, int wm, int wn, float acc[4][4][4])
{
    const uint32_t stb = sb + st * GSTAGE1;
#pragma unroll
    for (int ks = 0; ks < 4; ks++) {
        uint32_t ahf[4][4];
        const int arow = wm + (lane & 15);
        const int ac = ks * 2 + (lane >> 4);
#pragma unroll
        for (int mt = 0; mt < 4; mt++) {
            int r = arow + mt * 16;
            LDMX4(ahf[mt], stb + r * 128 + ((ac ^ (r & 7)) * 16));
        }
        const int brow0 = wn + ((lane >> 4) << 3) + (lane & 7);
        const int bc = ks * 2 + ((lane >> 3) & 1);
#pragma unroll
        for (int ntp = 0; ntp < 2; ntp++) {
            int r = brow0 + ntp * 16;
            uint32_t bhf[4];
            LDMX4(bhf, stb + 16384 + r * 128 + ((bc ^ (r & 7)) * 16));
#pragma unroll
            for (int hf = 0; hf < 2; hf++) {
                const int nt = ntp * 2 + hf;
#pragma unroll
                for (int mt = 0; mt < 4; mt++) MMA_BF16(acc[mt][nt], ahf[mt], &bhf[hf*2]);
            }
        }
    }
}

/* QKV projections: z selects q/k/v; out = bf16 in [b][h][s][d] */
__global__ __launch_bounds__(256, 2)
void qkv_gemm()
{
    extern __shared__ __align__(128) char smem[];
    const uint32_t sb = smem_to_u32(smem);
    const int tid = threadIdx.x;
    const int lane = tid & 31, wid = tid >> 5;
    const int wm = (wid >> 2) * 64, wn = (wid & 3) * 32;
    const int n0 = blockIdx.x * 128, m0 = blockIdx.y * 128;
    const int z = blockIdx.z;

    const __nv_bfloat16* Ah = (z == 0) ? bq_h : ((z == 1) ? bk_h : bv_h);
    const __nv_bfloat16* Bh = (z == 0) ? bwq_h : ((z == 1) ? bwk_h : bwv_h);
    __nv_bfloat16* Oh = (z == 0) ? oq_h : ((z == 1) ? ok_h : ov_h);

    float acc[4][4][4];
#pragma unroll
    for (int mt = 0; mt < 4; mt++)
#pragma unroll
        for (int nt = 0; nt < 4; nt++)
#pragma unroll
            for (int e = 0; e < 4; e++) acc[mt][nt][e] = 0.f;

    gemm1_load(sb, 0, 0, tid, m0, n0, Ah, Bh);
    CP_COMMIT();

    for (int kb = 0; kb < 16; kb++) {
        if (kb < 15) {
            gemm1_load(sb, (kb + 1) & 1, kb + 1, tid, m0, n0, Ah, Bh);
            CP_COMMIT();
            CP_WAIT1();
        } else {
            CP_WAIT0();
        }
        __syncthreads();
        gemm1_compute(sb, kb & 1, lane, wm, wn, acc);
        __syncthreads();
    }

    const int cr = lane >> 2, cc = (lane & 3) * 2;
    const int h = (n0 + wn) >> 6;
    const int d_base = (n0 + wn) & 63;
#pragma unroll
    for (int mt = 0; mt < 4; mt++) {
#pragma unroll
        for (int rr = 0; rr < 2; rr++) {
            const int m = m0 + wm + mt * 16 + cr + rr * 8;
            const int bb = m >> 11, s = m & 2047;
            size_t rowoff = (((size_t)bb * NHEAD + h) * SEQ + s) * DHEAD + d_base;
#pragma unroll
            for (int nt = 0; nt < 4; nt++) {
                int d = nt * 8 + cc;
                uint32_t pk;
                PACKBF2(pk, acc[mt][nt][rr*2], acc[mt][nt][rr*2+1]);
                *(uint32_t*)(Oh + rowoff + d) = pk;
            }
        }
    }
}

/* Output projection (single product) + residual -> g_pre */
__global__ __launch_bounds__(256, 2)
void out_gemm(const float* __restrict__ Res)
{
    extern __shared__ __align__(128) char smem[];
    const uint32_t sb = smem_to_u32(smem);
    const int tid = threadIdx.x;
    const int lane = tid & 31, wid = tid >> 5;
    const int wm = (wid >> 2) * 64, wn = (wid & 3) * 32;
    const int n0 = blockIdx.x * 128, m0 = blockIdx.y * 128;

    float acc[4][4][4];
#pragma unroll
    for (int mt = 0; mt < 4; mt++)
#pragma unroll
        for (int nt = 0; nt < 4; nt++)
#pragma unroll
            for (int e = 0; e < 4; e++) acc[mt][nt][e] = 0.f;

    gemm1_load(sb, 0, 0, tid, m0, n0, bctx_h, bwo_h);
    CP_COMMIT();

    for (int kb = 0; kb < 16; kb++) {
        if (kb < 15) {
            gemm1_load(sb, (kb + 1) & 1, kb + 1, tid, m0, n0, bctx_h, bwo_h);
            CP_COMMIT();
            CP_WAIT1();
        } else {
            CP_WAIT0();
        }
        __syncthreads();
        gemm1_compute(sb, kb & 1, lane, wm, wn, acc);
        __syncthreads();
    }

    const int cr = lane >> 2, cc = (lane & 3) * 2;
#pragma unroll
    for (int mt = 0; mt < 4; mt++) {
#pragma unroll
        for (int rr = 0; rr < 2; rr++) {
            const int m = m0 + wm + mt * 16 + cr + rr * 8;
            const float* rp = Res + (size_t)m * D_MODEL + n0 + wn;
            float* dst = g_pre + (size_t)m * D_MODEL + n0 + wn;
#pragma unroll
            for (int nt = 0; nt < 4; nt++) {
                int d = nt * 8 + cc;
                float2 rv = *(const float2*)(rp + d);
                *(float2*)(dst + d) = make_float2(acc[mt][nt][rr*2] + rv.x,
                                                  acc[mt][nt][rr*2+1] + rv.y);
            }
        }
    }
}

/* ============================================================
 * flash_mma: single-bf16, 128 Q rows/block, 4 warps x 32 rows,
 * K/V tile 64, 2-stage cp.async, static-offset softmax,
 * A-fragment reuse. (unchanged from R15)
 * ============================================================ */
#define FTHREADS   128
#define FSH_KV     16384
#define FKV_STAGE  16384
#define FSH_MSK    (16384 + 2*16384)   /* 49152 */
#define FLASH_SMEM (49152 + 512)

__device__ __forceinline__ void flash_load_kv(
    uint32_t sb, int st, int kt, int tid, size_t bh_base, const float* maskb)
{
    const int sk0 = kt * 64;
    const uint32_t stb = sb + FSH_KV + st * FKV_STAGE;
#pragma unroll
    for (int t = 0; t < 2; t++) {
        const __nv_bfloat16* S = (t ? ov_h : ok_h) + bh_base + (size_t)sk0 * DHEAD;
        const uint32_t dstb = stb + t * 8192;
#pragma unroll
        for (int it = 0; it < 4; it++) {
            int flat = tid + it * FTHREADS;
            int r = flat >> 3, c = flat & 7;
            const char* g = (const char*)(S + (size_t)r * DHEAD) + c * 16;
            CP_ASYNC16(dstb + r * 128 + ((c ^ (r & 7)) * 16), g);
        }
    }
    if (tid < 16)
        CP_ASYNC16(sb + FSH_MSK + st * 256 + tid * 16, maskb + sk0 + tid * 4);
}

__global__ __launch_bounds__(FTHREADS)
void flash_mma(const float* __restrict__ mask)
{
    extern __shared__ __align__(128) char fsm[];
    const uint32_t sb = smem_to_u32(fsm);

    const int tid = threadIdx.x;
    const int lane = tid & 31, wid = tid >> 5;
    const int wq = wid * 32;
    const int bh = blockIdx.y;
    const int b  = bh >> 4;
    const int h  = bh & 15;
    const int q0 = blockIdx.x * 128;
    const size_t bh_base = (size_t)bh * SEQ * DHEAD;
    const float* maskb = mask + b * SEQ;

    {
        const __nv_bfloat16* S = oq_h + bh_base + (size_t)q0 * DHEAD;
#pragma unroll
        for (int it = 0; it < 8; it++) {
            int flat = tid + it * FTHREADS;
            int r = flat >> 3, c = flat & 7;
            uint4 val = *(const uint4*)((const char*)(S + (size_t)r * DHEAD) + c * 16);
            uint32_t sw = sb + r * 128 + ((c ^ (r & 7)) * 16);
            asm volatile("st.shared.v4.b32 [%0], {%1,%2,%3,%4};"
                         :: "r"(sw), "r"(val.x), "r"(val.y), "r"(val.z), "r"(val.w));
        }
    }

    flash_load_kv(sb, 0, 0, tid, bh_base, maskb);
    CP_COMMIT();

    __syncthreads();
    uint32_t qfh[2][4][4];
#pragma unroll
    for (int ms = 0; ms < 2; ms++)
#pragma unroll
        for (int ks = 0; ks < 4; ks++) {
            const int ar = wq + ms * 16 + (lane & 15);
            const int ac = ks * 2 + (lane >> 4);
            LDMX4(qfh[ms][ks], sb + ar * 128 + ((ac ^ (ar & 7)) * 16));
        }

    float l[2][2] = {{0.f, 0.f}, {0.f, 0.f}};
    float o[2][8][4];
#pragma unroll
    for (int ms = 0; ms < 2; ms++)
#pragma unroll
        for (int nt = 0; nt < 8; nt++)
#pragma unroll
            for (int e = 0; e < 4; e++) o[ms][nt][e] = 0.f;

    const int c0 = (lane & 3) * 2;
    const float SCALE = 0.125f * LOG2E;
    const float MSCALE = -1e9f * LOG2E;
    const float FMAX_OFF = 16.0f;

    for (int kt = 0; kt < SEQ / 64; kt++) {
        const int st = kt & 1;
        if (kt < SEQ/64 - 1) {
            flash_load_kv(sb, st ^ 1, kt + 1, tid, bh_base, maskb);
            CP_COMMIT();
            CP_WAIT1();
        } else {
            CP_WAIT0();
        }
        __syncthreads();

        const uint32_t kvb = sb + FSH_KV + st * FKV_STAGE;
        const float* msk_s = (const float*)(fsm + FSH_MSK + st * 256);

        float s[2][8][4];
#pragma unroll
        for (int ms = 0; ms < 2; ms++)
#pragma unroll
            for (int nt = 0; nt < 8; nt++)
#pragma unroll
                for (int e = 0; e < 4; e++) s[ms][nt][e] = 0.f;
#pragma unroll
        for (int ks = 0; ks < 4; ks++) {
            const int brow0 = ((lane >> 4) << 3) + (lane & 7);
            const int bc = ks * 2 + ((lane >> 3) & 1);
#pragma unroll
            for (int ntp = 0; ntp < 4; ntp++) {
                int r = brow0 + ntp * 16;
                uint32_t bhf[4];
                LDMX4(bhf, kvb + r * 128 + ((bc ^ (r & 7)) * 16));
#pragma unroll
                for (int hf = 0; hf < 2; hf++)
#pragma unroll
                    for (int ms = 0; ms < 2; ms++)
                        MMA_BF16(s[ms][ntp*2 + hf], qfh[ms][ks], &bhf[hf*2]);
            }
        }

        uint32_t ah[2][4][4];
#pragma unroll
        for (int nt = 0; nt < 8; nt++) {
            float mv0 = fmaf(msk_s[nt*8 + c0],     MSCALE, -FMAX_OFF);
            float mv1 = fmaf(msk_s[nt*8 + c0 + 1], MSCALE, -FMAX_OFF);
#pragma unroll
            for (int ms = 0; ms < 2; ms++) {
                EX2(s[ms][nt][0], fmaf(s[ms][nt][0], SCALE, mv0));
                EX2(s[ms][nt][1], fmaf(s[ms][nt][1], SCALE, mv1));
                EX2(s[ms][nt][2], fmaf(s[ms][nt][2], SCALE, mv0));
                EX2(s[ms][nt][3], fmaf(s[ms][nt][3], SCALE, mv1));
                l[ms][0] += s[ms][nt][0] + s[ms][nt][1];
                l[ms][1] += s[ms][nt][2] + s[ms][nt][3];
                const int ks = nt >> 1, half = nt & 1;
                PACKBF2(ah[ms][ks][half*2 + 0], s[ms][nt][0], s[ms][nt][1]);
                PACKBF2(ah[ms][ks][half*2 + 1], s[ms][nt][2], s[ms][nt][3]);
            }
        }

#pragma unroll
        for (int ks = 0; ks < 4; ks++) {
            const int vr = ks*16 + (lane & 15);
            const int vc = (lane >> 4);
#pragma unroll
            for (int ntp = 0; ntp < 4; ntp++) {
                int c = ntp*2 + vc;
                uint32_t vh[4];
                LDMX4T(vh, kvb + 8192 + vr * 128 + ((c ^ (vr & 7)) * 16));
#pragma unroll
                for (int hf = 0; hf < 2; hf++)
#pragma unroll
                    for (int ms = 0; ms < 2; ms++)
                        MMA_BF16(o[ms][ntp*2 + hf], ah[ms][ks], &vh[hf*2]);
            }
        }
        __syncthreads();
    }

#pragma unroll
    for (int ms = 0; ms < 2; ms++) {
        l[ms][0] += __shfl_xor_sync(0xffffffffu, l[ms][0], 1);
        l[ms][0] += __shfl_xor_sync(0xffffffffu, l[ms][0], 2);
        l[ms][1] += __shfl_xor_sync(0xffffffffu, l[ms][1], 1);
        l[ms][1] += __shfl_xor_sync(0xffffffffu, l[ms][1], 2);
    }

#pragma unroll
    for (int ms = 0; ms < 2; ms++) {
        const float inv0 = 1.f / l[ms][0], inv1 = 1.f / l[ms][1];
        const int r0 = q0 + wq + ms * 16 + (lane >> 2);
        const size_t ro0 = ((size_t)b * SEQ + r0) * D_MODEL + h * DHEAD;
        const size_t ro1 = ((size_t)b * SEQ + r0 + 8) * D_MODEL + h * DHEAD;
#pragma unroll
        for (int nt = 0; nt < 8; nt++) {
            int d = nt * 8 + c0;
            uint32_t p0, p1;
            PACKBF2(p0, o[ms][nt][0] * inv0, o[ms][nt][1] * inv0);
            PACKBF2(p1, o[ms][nt][2] * inv1, o[ms][nt][3] * inv1);
            *(uint32_t*)(bctx_h + ro0 + d) = p0;
            *(uint32_t*)(bctx_h + ro1 + d) = p1;
        }
    }
}

/* ============================================================
 * LayerNorm
 * ============================================================ */
__global__ __launch_bounds__(256)
void ln_kernel(const float* __restrict__ gamma, const float* __restrict__ beta,
               float* __restrict__ out)
{
    const int row = blockIdx.x;
    const int tid = threadIdx.x;
    const float* x = &g_pre[(size_t)row * D_MODEL];

    float4 v = *(const float4*)&x[tid * 4];
    float s  = v.x + v.y + v.z + v.w;
    float ss = v.x*v.x + v.y*v.y + v.z*v.z + v.w*v.w;
#pragma unroll
    for (int off = 16; off >= 1; off >>= 1) {
        s  += __shfl_xor_sync(0xffffffffu, s, off);
        ss += __shfl_xor_sync(0xffffffffu, ss, off);
    }
    __shared__ float rs[8], rss[8];
    __shared__ float mu_s, inv_s;
    if ((tid & 31) == 0) { rs[tid >> 5] = s; rss[tid >> 5] = ss; }
    __syncthreads();
    if (tid == 0) {
        float S = 0.f, SS = 0.f;
#pragma unroll
        for (int i = 0; i < 8; i++) { S += rs[i]; SS += rss[i]; }
        float mu  = S * (1.f / D_MODEL);
        float var = SS * (1.f / D_MODEL) - mu * mu;
        mu_s = mu;
        inv_s = rsqrtf(var + LN_EPS);
    }
    __syncthreads();
    const float mu = mu_s, inv = inv_s;
    float4 g  = *(const float4*)&gamma[tid * 4];
    float4 be = *(const float4*)&beta[tid * 4];
    float4 r;
    r.x = (v.x - mu) * inv * g.x + be.x;
    r.y = (v.y - mu) * inv * g.y + be.y;
    r.z = (v.z - mu) * inv * g.z + be.z;
    r.w = (v.w - mu) * inv * g.w + be.w;
    *(float4*)&out[(size_t)row * D_MODEL + tid * 4] = r;
}

/* ============================================================ */
extern "C" void kernel_launch(void* const* d_in, const int* in_sizes, int n_in,
                              void* d_out, int out_size)
{
    const float* q     = (const float*)d_in[0];
    const float* k     = (const float*)d_in[1];
    const float* v     = (const float*)d_in[2];
    const float* mask  = (const float*)d_in[3];
    const float* Wq    = (const float*)d_in[4];
    const float* Wk    = (const float*)d_in[5];
    const float* Wv    = (const float*)d_in[6];
    const float* Wo    = (const float*)d_in[7];
    const float* gamma = (const float*)d_in[8];
    const float* beta  = (const float*)d_in[9];
    float* out = (float*)d_out;

    cudaFuncSetAttribute(qkv_gemm, cudaFuncAttributeMaxDynamicSharedMemorySize, GEMM1_SMEM);
    cudaFuncSetAttribute(out_gemm, cudaFuncAttributeMaxDynamicSharedMemorySize, GEMM1_SMEM);
    cudaFuncSetAttribute(flash_mma, cudaFuncAttributeMaxDynamicSharedMemorySize, FLASH_SMEM);

    const int NA4 = M_TOTAL*D_MODEL/4;
    const int NW4 = D_MODEL*D_MODEL/4;

    act_conv<<<dim3(NA4/256, 3), 256>>>(q, k, v);
    w_conv<<<dim3(NW4/256, 4), 256>>>(Wq, Wk, Wv, Wo);

    qkv_gemm<<<dim3(D_MODEL/128, M_TOTAL/128, 3), 256, GEMM1_SMEM>>>();

    flash_mma<<<dim3(SEQ/128, BSZ*NHEAD), FTHREADS, FLASH_SMEM>>>(mask);

    out_gemm<<<dim3(D_MODEL/128, M_TOTAL/128), 256, GEMM1_SMEM>>>(q);

    ln_kernel<<<M_TOTAL, 256>>>(gamma, beta, out);
}